// round 1
// baseline (speedup 1.0000x reference)
#include <cuda_runtime.h>
#include <cstdint>
#include <cstddef>

#define HW     16384
#define WIMG   128
#define DIM    192
#define CDIM   576
#define NB     8
#define NHEAD  8
#define NBH    192      // NB * 3 * NHEAD
#define NSLICE 16

// ---------------- scratch (device globals; no allocations allowed) ----------
__device__ float g_qkv  [NB*CDIM*HW];
__device__ float g_conv0[NB*CDIM*HW];
__device__ float g_conv1[NB*CDIM*HW];
__device__ float g_conv2[NB*CDIM*HW];
__device__ float g_partS [NBH*NSLICE*24*24];
__device__ float g_partQQ[NBH*NSLICE*24];
__device__ float g_partKK[NBH*NSLICE*24];
__device__ float g_attn [NBH*24*24];
__device__ float g_M    [NB*DIM*CDIM];

// ---------------- kernel 1: qkv = W_qkv @ X  (per batch 576x192 @ 192x16384)
__global__ __launch_bounds__(256) void k_gemm_qkv(const float* __restrict__ A,
                                                  const float* __restrict__ X) {
    __shared__ float As[16][64];
    __shared__ float Bs[16][128];
    const int b  = blockIdx.z;
    const int m0 = blockIdx.y * 64;
    const int n0 = blockIdx.x * 128;
    const float* Bb = X + (size_t)b * DIM * HW;
    float*       Cb = g_qkv + (size_t)b * CDIM * HW;
    const int tid = threadIdx.x;
    const int tm = tid >> 4, tn = tid & 15;

    float acc[4][8];
#pragma unroll
    for (int i = 0; i < 4; i++)
#pragma unroll
        for (int j = 0; j < 8; j++) acc[i][j] = 0.f;

    for (int k0 = 0; k0 < DIM; k0 += 16) {
        {
            int am = tid >> 2, ak = (tid & 3) << 2;
            float4 a4 = *(const float4*)(A + (size_t)(m0 + am) * DIM + k0 + ak);
            As[ak + 0][am] = a4.x; As[ak + 1][am] = a4.y;
            As[ak + 2][am] = a4.z; As[ak + 3][am] = a4.w;
        }
#pragma unroll
        for (int i = 0; i < 2; i++) {
            int idx = tid + (i << 8);
            int kk = idx >> 5, c4 = (idx & 31) << 2;
            *(float4*)&Bs[kk][c4] =
                *(const float4*)(Bb + (size_t)(k0 + kk) * HW + n0 + c4);
        }
        __syncthreads();
#pragma unroll
        for (int k = 0; k < 16; k++) {
            float4 av = *(float4*)&As[k][tm << 2];
            float4 b0 = *(float4*)&Bs[k][tn << 3];
            float4 b1 = *(float4*)&Bs[k][(tn << 3) + 4];
            float ar[4] = {av.x, av.y, av.z, av.w};
            float br[8] = {b0.x, b0.y, b0.z, b0.w, b1.x, b1.y, b1.z, b1.w};
#pragma unroll
            for (int i = 0; i < 4; i++)
#pragma unroll
                for (int j = 0; j < 8; j++)
                    acc[i][j] = fmaf(ar[i], br[j], acc[i][j]);
        }
        __syncthreads();
    }
#pragma unroll
    for (int i = 0; i < 4; i++) {
        float* cp = Cb + (size_t)(m0 + (tm << 2) + i) * HW + n0 + (tn << 3);
        *(float4*)cp       = make_float4(acc[i][0], acc[i][1], acc[i][2], acc[i][3]);
        *(float4*)(cp + 4) = make_float4(acc[i][4], acc[i][5], acc[i][6], acc[i][7]);
    }
}

// ---------------- kernel 2: fused depthwise 3x3, dilations 1/2/3 ------------
template <int D>
__device__ __forceinline__ void conv3x3_d(const float v[7][12],
                                          const float* __restrict__ w, float o[4]) {
    float wr[9];
#pragma unroll
    for (int i = 0; i < 9; i++) wr[i] = __ldg(w + i);
#pragma unroll
    for (int x = 0; x < 4; x++) {
        float s = 0.f;
#pragma unroll
        for (int ky = 0; ky < 3; ky++)
#pragma unroll
            for (int kx = 0; kx < 3; kx++)
                s = fmaf(v[3 + (ky - 1) * D][4 + x + (kx - 1) * D], wr[ky * 3 + kx], s);
        o[x] = s;
    }
}

__global__ __launch_bounds__(256) void k_dwconv(const float* __restrict__ w1,
                                                const float* __restrict__ w2,
                                                const float* __restrict__ w3) {
    int gid = blockIdx.x * 256 + threadIdx.x;          // 18,874,368 total
    int xg = gid & 31;
    int y  = (gid >> 5) & 127;
    int bc = gid >> 12;                                 // b*576 + ch, 0..4607
    int ch = bc % CDIM;
    const float* in = g_qkv + (size_t)bc * HW;
    int x0 = xg << 2;

    float v[7][12];
#pragma unroll
    for (int r = 0; r < 7; r++) {
        int yy = y + r - 3;
        if (yy < 0 || yy > 127) {
#pragma unroll
            for (int j = 0; j < 12; j++) v[r][j] = 0.f;
        } else {
            const float* rp = in + yy * WIMG;
            float4 f0 = (x0 == 0)   ? make_float4(0, 0, 0, 0) : *(const float4*)(rp + x0 - 4);
            float4 f1 = *(const float4*)(rp + x0);
            float4 f2 = (x0 == 124) ? make_float4(0, 0, 0, 0) : *(const float4*)(rp + x0 + 4);
            v[r][0] = f0.x; v[r][1] = f0.y; v[r][2]  = f0.z; v[r][3]  = f0.w;
            v[r][4] = f1.x; v[r][5] = f1.y; v[r][6]  = f1.z; v[r][7]  = f1.w;
            v[r][8] = f2.x; v[r][9] = f2.y; v[r][10] = f2.z; v[r][11] = f2.w;
        }
    }
    size_t obase = (size_t)bc * HW + y * WIMG + x0;
    float o[4];
    conv3x3_d<1>(v, w1 + ch * 9, o);
    *(float4*)(g_conv0 + obase) = make_float4(o[0], o[1], o[2], o[3]);
    conv3x3_d<2>(v, w2 + ch * 9, o);
    *(float4*)(g_conv1 + obase) = make_float4(o[0], o[1], o[2], o[3]);
    conv3x3_d<3>(v, w3 + ch * 9, o);
    *(float4*)(g_conv2 + obase) = make_float4(o[0], o[1], o[2], o[3]);
}

// ---------------- kernel 3: per (b,branch,head) Gram Q·K^T + norms, split-K -
__global__ __launch_bounds__(64) void k_gram() {
    const int bh = blockIdx.x;               // b*24 + br*8 + head
    const int slice = blockIdx.y;            // 16 slices of 1024 n each
    const int b = bh / 24, rem = bh % 24;
    const int br = rem >> 3, head = rem & 7;
    const float* conv = (br == 0) ? g_conv0 : (br == 1) ? g_conv1 : g_conv2;
    const float* qb = conv + (size_t)(b * CDIM + head * 24) * HW;
    const float* kb = conv + (size_t)(b * CDIM + 192 + head * 24) * HW;

    __shared__ __align__(16) float qs[24 * 130];
    __shared__ __align__(16) float ks[24 * 130];

    const int tid = threadIdx.x;
    const int rg = tid >> 3, cg = tid & 7;   // 8x8 groups of 3x3 over 24x24
    float acc[3][3] = {};
    float qq[3] = {}, kk[3] = {};
    const int n0s = slice * 1024;

    for (int cch = 0; cch < 8; cch++) {
        const int n0 = n0s + cch * 128;
#pragma unroll
        for (int i = 0; i < 12; i++) {
            int idx = (i << 6) + tid;
            int row = idx >> 5, c4 = (idx & 31) << 2;
            float4 qv = *(const float4*)(qb + (size_t)row * HW + n0 + c4);
            float4 kv = *(const float4*)(kb + (size_t)row * HW + n0 + c4);
            float* qp = &qs[row * 130 + c4];
            qp[0] = qv.x; qp[1] = qv.y; qp[2] = qv.z; qp[3] = qv.w;
            float* kp = &ks[row * 130 + c4];
            kp[0] = kv.x; kp[1] = kv.y; kp[2] = kv.z; kp[3] = kv.w;
        }
        __syncthreads();
#pragma unroll 4
        for (int n = 0; n < 128; n += 2) {
            float2 qv[3], kv[3];
#pragma unroll
            for (int i = 0; i < 3; i++) {
                qv[i] = *(float2*)&qs[(rg * 3 + i) * 130 + n];
                kv[i] = *(float2*)&ks[(cg * 3 + i) * 130 + n];
            }
#pragma unroll
            for (int i = 0; i < 3; i++)
#pragma unroll
                for (int j = 0; j < 3; j++)
                    acc[i][j] += qv[i].x * kv[j].x + qv[i].y * kv[j].y;
            if (cg == 0) {
#pragma unroll
                for (int i = 0; i < 3; i++)
                    qq[i] += qv[i].x * qv[i].x + qv[i].y * qv[i].y;
            }
            if (rg == 0) {
#pragma unroll
                for (int j = 0; j < 3; j++)
                    kk[j] += kv[j].x * kv[j].x + kv[j].y * kv[j].y;
            }
        }
        __syncthreads();
    }
    const int base = (bh * NSLICE + slice) * 24;
#pragma unroll
    for (int i = 0; i < 3; i++)
#pragma unroll
        for (int j = 0; j < 3; j++)
            g_partS[(size_t)(base + rg * 3 + i) * 24 + cg * 3 + j] = acc[i][j];
    if (cg == 0)
#pragma unroll
        for (int i = 0; i < 3; i++) g_partQQ[base + rg * 3 + i] = qq[i];
    if (rg == 0)
#pragma unroll
        for (int j = 0; j < 3; j++) g_partKK[base + cg * 3 + j] = kk[j];
}

// ---------------- kernel 4: reduce partials, normalize, temperature, softmax
__global__ __launch_bounds__(576) void k_softmax(const float* __restrict__ temperature) {
    const int bh = blockIdx.x;
    const int head = bh & 7;
    const int t = threadIdx.x;
    const int c = t / 24, d = t % 24;

    float s = 0.f;
    for (int sl = 0; sl < NSLICE; sl++)
        s += g_partS[(size_t)((bh * NSLICE + sl) * 24 + c) * 24 + d];

    __shared__ float nq[24], nk[24], logits[576], rmax[24], rsum[24];
    if (t < 24) {
        float a = 0.f, b2 = 0.f;
        for (int sl = 0; sl < NSLICE; sl++) {
            a  += g_partQQ[(bh * NSLICE + sl) * 24 + t];
            b2 += g_partKK[(bh * NSLICE + sl) * 24 + t];
        }
        nq[t] = fmaxf(sqrtf(a),  1e-12f);
        nk[t] = fmaxf(sqrtf(b2), 1e-12f);
    }
    __syncthreads();
    float lg = s / (nq[c] * nk[d]) * temperature[head];
    logits[t] = lg;
    __syncthreads();
    if (d == 0) {
        float mx = -1e30f;
        for (int j = 0; j < 24; j++) mx = fmaxf(mx, logits[c * 24 + j]);
        float sm = 0.f;
        for (int j = 0; j < 24; j++) sm += expf(logits[c * 24 + j] - mx);
        rmax[c] = mx; rsum[c] = sm;
    }
    __syncthreads();
    g_attn[(size_t)bh * 576 + t] = expf(lg - rmax[c]) / rsum[c];
}

// ---------------- kernel 5: fold proj into attn: M[b,o,col] ------------------
__global__ __launch_bounds__(192) void k_buildM(const float* __restrict__ wproj) {
    const int blk = blockIdx.x;              // b*24 + br*8 + head
    const int b = blk / 24, rem = blk % 24;
    const int br = rem >> 3, head = rem & 7;
    __shared__ float at[576];
    const int t = threadIdx.x;
#pragma unroll
    for (int i = 0; i < 3; i++) at[t + i * 192] = g_attn[(size_t)blk * 576 + t + i * 192];
    __syncthreads();
    const int colbase = br * 192 + head * 24;
    const float* wrow = wproj + (size_t)t * CDIM + colbase;
    float* mrow = g_M + ((size_t)b * DIM + t) * CDIM + colbase;
#pragma unroll 4
    for (int d = 0; d < 24; d++) {
        float s = 0.f;
#pragma unroll
        for (int cc = 0; cc < 24; cc++) s = fmaf(wrow[cc], at[cc * 24 + d], s);
        mrow[d] = s;
    }
}

// ---------------- kernel 6: out = M_b @ V_b (V gathered from conv v-halves) --
__global__ __launch_bounds__(256) void k_gemm_out(float* __restrict__ Out) {
    __shared__ float As[16][64];
    __shared__ float Bs[16][128];
    const int b  = blockIdx.z;
    const int m0 = blockIdx.y * 64;
    const int n0 = blockIdx.x * 128;
    const float* A = g_M + (size_t)b * DIM * CDIM;
    float*       Cb = Out + (size_t)b * DIM * HW;
    const int tid = threadIdx.x;
    const int tm = tid >> 4, tn = tid & 15;

    float acc[4][8];
#pragma unroll
    for (int i = 0; i < 4; i++)
#pragma unroll
        for (int j = 0; j < 8; j++) acc[i][j] = 0.f;

    for (int k0 = 0; k0 < CDIM; k0 += 16) {
        {
            int am = tid >> 2, ak = (tid & 3) << 2;
            float4 a4 = *(const float4*)(A + (size_t)(m0 + am) * CDIM + k0 + ak);
            As[ak + 0][am] = a4.x; As[ak + 1][am] = a4.y;
            As[ak + 2][am] = a4.z; As[ak + 3][am] = a4.w;
        }
#pragma unroll
        for (int i = 0; i < 2; i++) {
            int idx = tid + (i << 8);
            int kk = idx >> 5, c4 = (idx & 31) << 2;
            int r = k0 + kk;                          // 0..575
            int brn = (r >= 384) ? 2 : (r >= 192) ? 1 : 0;
            int ch  = r - brn * 192;
            const float* conv = (brn == 0) ? g_conv0 : (brn == 1) ? g_conv1 : g_conv2;
            const float* rowp = conv + (size_t)(b * CDIM + 384 + ch) * HW;
            *(float4*)&Bs[kk][c4] = *(const float4*)(rowp + n0 + c4);
        }
        __syncthreads();
#pragma unroll
        for (int k = 0; k < 16; k++) {
            float4 av = *(float4*)&As[k][tm << 2];
            float4 b0 = *(float4*)&Bs[k][tn << 3];
            float4 b1 = *(float4*)&Bs[k][(tn << 3) + 4];
            float ar[4] = {av.x, av.y, av.z, av.w};
            float br[8] = {b0.x, b0.y, b0.z, b0.w, b1.x, b1.y, b1.z, b1.w};
#pragma unroll
            for (int i = 0; i < 4; i++)
#pragma unroll
                for (int j = 0; j < 8; j++)
                    acc[i][j] = fmaf(ar[i], br[j], acc[i][j]);
        }
        __syncthreads();
    }
#pragma unroll
    for (int i = 0; i < 4; i++) {
        float* cp = Cb + (size_t)(m0 + (tm << 2) + i) * HW + n0 + (tn << 3);
        *(float4*)cp       = make_float4(acc[i][0], acc[i][1], acc[i][2], acc[i][3]);
        *(float4*)(cp + 4) = make_float4(acc[i][4], acc[i][5], acc[i][6], acc[i][7]);
    }
}

// ---------------- launch ----------------------------------------------------
extern "C" void kernel_launch(void* const* d_in, const int* in_sizes, int n_in,
                              void* d_out, int out_size) {
    const float* x       = (const float*)d_in[0];
    const float* w_qkv   = (const float*)d_in[1];
    const float* w_dw1   = (const float*)d_in[2];
    const float* w_dw2   = (const float*)d_in[3];
    const float* w_dw3   = (const float*)d_in[4];
    const float* w_proj  = (const float*)d_in[5];
    const float* temp    = (const float*)d_in[6];
    float* out = (float*)d_out;

    k_gemm_qkv<<<dim3(HW / 128, CDIM / 64, NB), 256>>>(w_qkv, x);
    k_dwconv<<<(NB * CDIM * WIMG * (WIMG / 4)) / 256, 256>>>(w_dw1, w_dw2, w_dw3);
    k_gram<<<dim3(NBH, NSLICE), 64>>>();
    k_softmax<<<NBH, 576>>>(temp);
    k_buildM<<<NBH, 192>>>(w_proj);
    k_gemm_out<<<dim3(HW / 128, DIM / 64, NB), 256>>>(out);
}

// round 3
// speedup vs baseline: 2.2447x; 2.2447x over previous
#include <cuda_runtime.h>
#include <cstdint>
#include <cstddef>

#define HW     16384
#define WIMG   128
#define DIM    192
#define CDIM   576
#define NB     8
#define NHEAD  8
#define NBH    192      // NB * 3 * NHEAD
#define NSLICE 16

// ---------------- scratch (device globals; no allocations allowed) ----------
__device__ float g_qkv  [NB*CDIM*HW];
__device__ float g_conv0[NB*CDIM*HW];
__device__ float g_conv1[NB*CDIM*HW];
__device__ float g_conv2[NB*CDIM*HW];
__device__ float g_partS [NBH*NSLICE*24*24];
__device__ float g_partQQ[NBH*NSLICE*24];
__device__ float g_partKK[NBH*NSLICE*24];
__device__ float g_attn [NBH*24*24];
__device__ float g_M    [NB*DIM*CDIM];

// ======================= helpers ============================================
__device__ __forceinline__ uint32_t smem_u32(const void* p) {
    uint32_t a;
    asm("{ .reg .u64 t; cvta.to.shared.u64 t, %1; cvt.u32.u64 %0, t; }"
        : "=r"(a) : "l"(p));
    return a;
}
__device__ __forceinline__ void cp_async16(uint32_t dst, const void* src, int src_sz) {
    asm volatile("cp.async.ca.shared.global [%0], [%1], 16, %2;"
                 :: "r"(dst), "l"(src), "r"(src_sz));
}
#define CP_COMMIT()  asm volatile("cp.async.commit_group;" ::: "memory")
#define CP_WAIT(n)   asm volatile("cp.async.wait_group %0;" :: "n"(n) : "memory")

__device__ __forceinline__ uint32_t f2tf32(float f) {
    uint32_t u;
    asm("cvt.rna.tf32.f32 %0, %1;" : "=r"(u) : "f"(f));
    return u;
}
__device__ __forceinline__ void mma_tf32(float d[4], const uint32_t a[4],
                                         uint32_t b0, uint32_t b1) {
    asm volatile(
        "mma.sync.aligned.m16n8k8.row.col.f32.tf32.tf32.f32 "
        "{%0,%1,%2,%3}, {%4,%5,%6,%7}, {%8,%9}, {%0,%1,%2,%3};"
        : "+f"(d[0]), "+f"(d[1]), "+f"(d[2]), "+f"(d[3])
        : "r"(a[0]), "r"(a[1]), "r"(a[2]), "r"(a[3]), "r"(b0), "r"(b1));
}

// ======================= tensor GEMM (mma.sync tf32) ========================
// MODE 0: g_qkv[b,576,HW] = W_qkv[576,192] @ X[b,192,HW]
// MODE 1: out[b,192,HW]   = g_M[b,192,576] @ V[b,576,HW]  (V from conv v-halves)
// CTA: 256 thr (8 warps 2x4), tile M128 x N256, K chunks of 32, double buffer.
#define AS_STRIDE 36     // 32 k + 4 pad  -> a-frag LDS conflict-free
#define BS_STRIDE 264    // 256 n + 8 pad -> b-frag LDS conflict-free
#define AS_ELEMS  (128 * AS_STRIDE)       // 4608 floats
#define BS_ELEMS  (32 * BS_STRIDE)        // 8448 floats
#define GEMM_SMEM_BYTES ((2 * (AS_ELEMS + BS_ELEMS)) * 4)   // 104448 B

template <int MODE>
__global__ __launch_bounds__(256, 1) void k_mma_gemm(const float* __restrict__ Amat,
                                                     const float* __restrict__ Xin,
                                                     float* __restrict__ Cout) {
    constexpr int KTOT = MODE ? CDIM : DIM;   // 576 / 192
    constexpr int NC   = KTOT / 32;           // 18 / 6
    constexpr int MLIM = MODE ? DIM : CDIM;   // 192 / 576

    extern __shared__ float sm[];
    const uint32_t sb = smem_u32(sm);
    // float offsets
    const uint32_t a_off[2] = {0u, AS_ELEMS};
    const uint32_t b_off[2] = {2u * AS_ELEMS, 2u * AS_ELEMS + BS_ELEMS};

    const int tid = threadIdx.x;
    const int n0  = blockIdx.x * 256;
    const int m0  = blockIdx.y * 128;
    const int b   = blockIdx.z;

    const int warp = tid >> 5, lane = tid & 31;
    const int gid = lane >> 2, tg = lane & 3;
    const int m_w = (warp >> 2) * 64;         // 0 / 64
    const int n_w = (warp & 3) * 64;          // 0..192

    const float* Arow = MODE ? (g_M + (size_t)b * DIM * CDIM) : Amat;

    // ------ chunk fill (cp.async) ------
    auto fill = [&](int cc) {
        const int buf = cc & 1;
        const int k0 = cc * 32;
        // A: 128 rows x 32 k, 16B tasks
#pragma unroll
        for (int i = 0; i < 4; i++) {
            int tsk = tid + (i << 8);
            int row = tsk >> 3, seg = tsk & 7;
            int mg = m0 + row;
            bool ok = (mg < MLIM);
            const float* src = Arow + (size_t)(ok ? mg : 0) * KTOT + k0 + seg * 4;
            uint32_t dst = sb + (a_off[buf] + row * AS_STRIDE + seg * 4) * 4;
            cp_async16(dst, src, ok ? 16 : 0);
        }
        // B: 32 k rows x 256 n, 16B tasks
#pragma unroll
        for (int i = 0; i < 8; i++) {
            int tsk = tid + (i << 8);
            int krow = tsk >> 6, seg = tsk & 63;
            int kg = k0 + krow;
            const float* src;
            if (MODE == 0) {
                src = Xin + ((size_t)(b * DIM + kg)) * HW + n0 + seg * 4;
            } else {
                int br = (kg >= 384) ? 2 : (kg >= 192) ? 1 : 0;
                int ch = kg - br * 192;
                const float* cv = (br == 0) ? g_conv0 : (br == 1) ? g_conv1 : g_conv2;
                src = cv + ((size_t)(b * CDIM + 384 + ch)) * HW + n0 + seg * 4;
            }
            uint32_t dst = sb + (b_off[buf] + krow * BS_STRIDE + seg * 4) * 4;
            cp_async16(dst, src, 16);
        }
    };

    float acc[4][8][4];
#pragma unroll
    for (int mt = 0; mt < 4; mt++)
#pragma unroll
        for (int nt = 0; nt < 8; nt++)
#pragma unroll
            for (int r = 0; r < 4; r++) acc[mt][nt][r] = 0.f;

    fill(0);
    CP_COMMIT();

#pragma unroll 1
    for (int cc = 0; cc < NC; cc++) {
        if (cc + 1 < NC) { fill(cc + 1); CP_COMMIT(); CP_WAIT(1); }
        else             { CP_WAIT(0); }
        __syncthreads();

        const float* As = sm + a_off[cc & 1];
        const float* Bs = sm + b_off[cc & 1];
#pragma unroll
        for (int k8 = 0; k8 < 4; k8++) {
            uint32_t a[4][4];
#pragma unroll
            for (int mt = 0; mt < 4; mt++) {
                const float* ap = As + (m_w + mt * 16 + gid) * AS_STRIDE + k8 * 8 + tg;
                a[mt][0] = f2tf32(ap[0]);
                a[mt][1] = f2tf32(ap[8 * AS_STRIDE]);
                a[mt][2] = f2tf32(ap[4]);
                a[mt][3] = f2tf32(ap[8 * AS_STRIDE + 4]);
            }
#pragma unroll
            for (int nt = 0; nt < 8; nt++) {
                const float* bp = Bs + (k8 * 8 + tg) * BS_STRIDE + n_w + nt * 8 + gid;
                uint32_t b0 = f2tf32(bp[0]);
                uint32_t b1 = f2tf32(bp[4 * BS_STRIDE]);
#pragma unroll
                for (int mt = 0; mt < 4; mt++)
                    mma_tf32(acc[mt][nt], a[mt], b0, b1);
            }
        }
        __syncthreads();
    }

    // ------ epilogue: direct fp32 stores (8B per thread per tile-half) ------
    float* Cbase = MODE ? (Cout + (size_t)b * DIM * HW)
                        : (g_qkv + (size_t)b * CDIM * HW);
#pragma unroll
    for (int mt = 0; mt < 4; mt++) {
        int mg0 = m0 + m_w + mt * 16 + gid;
        int mg1 = mg0 + 8;
#pragma unroll
        for (int nt = 0; nt < 8; nt++) {
            int n = n0 + n_w + nt * 8 + tg * 2;
            if (mg0 < MLIM)
                *(float2*)(Cbase + (size_t)mg0 * HW + n) =
                    make_float2(acc[mt][nt][0], acc[mt][nt][1]);
            if (mg1 < MLIM)
                *(float2*)(Cbase + (size_t)mg1 * HW + n) =
                    make_float2(acc[mt][nt][2], acc[mt][nt][3]);
        }
    }
}

// ---------------- fused depthwise 3x3, dilations 1/2/3 ----------------------
template <int D>
__device__ __forceinline__ void conv3x3_d(const float v[7][12],
                                          const float* __restrict__ w, float o[4]) {
    float wr[9];
#pragma unroll
    for (int i = 0; i < 9; i++) wr[i] = __ldg(w + i);
#pragma unroll
    for (int x = 0; x < 4; x++) {
        float s = 0.f;
#pragma unroll
        for (int ky = 0; ky < 3; ky++)
#pragma unroll
            for (int kx = 0; kx < 3; kx++)
                s = fmaf(v[3 + (ky - 1) * D][4 + x + (kx - 1) * D], wr[ky * 3 + kx], s);
        o[x] = s;
    }
}

__global__ __launch_bounds__(256) void k_dwconv(const float* __restrict__ w1,
                                                const float* __restrict__ w2,
                                                const float* __restrict__ w3) {
    int gid = blockIdx.x * 256 + threadIdx.x;
    int xg = gid & 31;
    int y  = (gid >> 5) & 127;
    int bc = gid >> 12;
    int ch = bc % CDIM;
    const float* in = g_qkv + (size_t)bc * HW;
    int x0 = xg << 2;

    float v[7][12];
#pragma unroll
    for (int r = 0; r < 7; r++) {
        int yy = y + r - 3;
        if (yy < 0 || yy > 127) {
#pragma unroll
            for (int j = 0; j < 12; j++) v[r][j] = 0.f;
        } else {
            const float* rp = in + yy * WIMG;
            float4 f0 = (x0 == 0)   ? make_float4(0, 0, 0, 0) : *(const float4*)(rp + x0 - 4);
            float4 f1 = *(const float4*)(rp + x0);
            float4 f2 = (x0 == 124) ? make_float4(0, 0, 0, 0) : *(const float4*)(rp + x0 + 4);
            v[r][0] = f0.x; v[r][1] = f0.y; v[r][2]  = f0.z; v[r][3]  = f0.w;
            v[r][4] = f1.x; v[r][5] = f1.y; v[r][6]  = f1.z; v[r][7]  = f1.w;
            v[r][8] = f2.x; v[r][9] = f2.y; v[r][10] = f2.z; v[r][11] = f2.w;
        }
    }
    size_t obase = (size_t)bc * HW + y * WIMG + x0;
    float o[4];
    conv3x3_d<1>(v, w1 + ch * 9, o);
    *(float4*)(g_conv0 + obase) = make_float4(o[0], o[1], o[2], o[3]);
    conv3x3_d<2>(v, w2 + ch * 9, o);
    *(float4*)(g_conv1 + obase) = make_float4(o[0], o[1], o[2], o[3]);
    conv3x3_d<3>(v, w3 + ch * 9, o);
    *(float4*)(g_conv2 + obase) = make_float4(o[0], o[1], o[2], o[3]);
}

// ---------------- Gram Q·K^T + norms, split-K --------------------------------
__global__ __launch_bounds__(64) void k_gram() {
    const int bh = blockIdx.x;
    const int slice = blockIdx.y;
    const int b = bh / 24, rem = bh % 24;
    const int br = rem >> 3, head = rem & 7;
    const float* conv = (br == 0) ? g_conv0 : (br == 1) ? g_conv1 : g_conv2;
    const float* qb = conv + (size_t)(b * CDIM + head * 24) * HW;
    const float* kb = conv + (size_t)(b * CDIM + 192 + head * 24) * HW;

    __shared__ __align__(16) float qs[24 * 130];
    __shared__ __align__(16) float ks[24 * 130];

    const int tid = threadIdx.x;
    const int rg = tid >> 3, cg = tid & 7;
    float acc[3][3] = {};
    float qq[3] = {}, kk[3] = {};
    const int n0s = slice * 1024;

    for (int cch = 0; cch < 8; cch++) {
        const int n0 = n0s + cch * 128;
#pragma unroll
        for (int i = 0; i < 12; i++) {
            int idx = (i << 6) + tid;
            int row = idx >> 5, c4 = (idx & 31) << 2;
            float4 qv = *(const float4*)(qb + (size_t)row * HW + n0 + c4);
            float4 kv = *(const float4*)(kb + (size_t)row * HW + n0 + c4);
            float* qp = &qs[row * 130 + c4];
            qp[0] = qv.x; qp[1] = qv.y; qp[2] = qv.z; qp[3] = qv.w;
            float* kp = &ks[row * 130 + c4];
            kp[0] = kv.x; kp[1] = kv.y; kp[2] = kv.z; kp[3] = kv.w;
        }
        __syncthreads();
#pragma unroll 4
        for (int n = 0; n < 128; n += 2) {
            float2 qv[3], kv[3];
#pragma unroll
            for (int i = 0; i < 3; i++) {
                qv[i] = *(float2*)&qs[(rg * 3 + i) * 130 + n];
                kv[i] = *(float2*)&ks[(cg * 3 + i) * 130 + n];
            }
#pragma unroll
            for (int i = 0; i < 3; i++)
#pragma unroll
                for (int j = 0; j < 3; j++)
                    acc[i][j] += qv[i].x * kv[j].x + qv[i].y * kv[j].y;
            if (cg == 0) {
#pragma unroll
                for (int i = 0; i < 3; i++)
                    qq[i] += qv[i].x * qv[i].x + qv[i].y * qv[i].y;
            }
            if (rg == 0) {
#pragma unroll
                for (int j = 0; j < 3; j++)
                    kk[j] += kv[j].x * kv[j].x + kv[j].y * kv[j].y;
            }
        }
        __syncthreads();
    }
    const int base = (bh * NSLICE + slice) * 24;
#pragma unroll
    for (int i = 0; i < 3; i++)
#pragma unroll
        for (int j = 0; j < 3; j++)
            g_partS[(size_t)(base + rg * 3 + i) * 24 + cg * 3 + j] = acc[i][j];
    if (cg == 0)
#pragma unroll
        for (int i = 0; i < 3; i++) g_partQQ[base + rg * 3 + i] = qq[i];
    if (rg == 0)
#pragma unroll
        for (int j = 0; j < 3; j++) g_partKK[base + cg * 3 + j] = kk[j];
}

// ---------------- reduce, normalize, temperature, softmax --------------------
__global__ __launch_bounds__(576) void k_softmax(const float* __restrict__ temperature) {
    const int bh = blockIdx.x;
    const int head = bh & 7;
    const int t = threadIdx.x;
    const int c = t / 24, d = t % 24;

    float s = 0.f;
    for (int sl = 0; sl < NSLICE; sl++)
        s += g_partS[(size_t)((bh * NSLICE + sl) * 24 + c) * 24 + d];

    __shared__ float nq[24], nk[24], logits[576], rmax[24], rsum[24];
    if (t < 24) {
        float a = 0.f, b2 = 0.f;
        for (int sl = 0; sl < NSLICE; sl++) {
            a  += g_partQQ[(bh * NSLICE + sl) * 24 + t];
            b2 += g_partKK[(bh * NSLICE + sl) * 24 + t];
        }
        nq[t] = fmaxf(sqrtf(a),  1e-12f);
        nk[t] = fmaxf(sqrtf(b2), 1e-12f);
    }
    __syncthreads();
    float lg = s / (nq[c] * nk[d]) * temperature[head];
    logits[t] = lg;
    __syncthreads();
    if (d == 0) {
        float mx = -1e30f;
        for (int j = 0; j < 24; j++) mx = fmaxf(mx, logits[c * 24 + j]);
        float sm = 0.f;
        for (int j = 0; j < 24; j++) sm += expf(logits[c * 24 + j] - mx);
        rmax[c] = mx; rsum[c] = sm;
    }
    __syncthreads();
    g_attn[(size_t)bh * 576 + t] = expf(lg - rmax[c]) / rsum[c];
}

// ---------------- fold proj into attn: M[b,o,col] ----------------------------
__global__ __launch_bounds__(192) void k_buildM(const float* __restrict__ wproj) {
    const int blk = blockIdx.x;
    const int b = blk / 24, rem = blk % 24;
    const int br = rem >> 3, head = rem & 7;
    __shared__ float at[576];
    const int t = threadIdx.x;
#pragma unroll
    for (int i = 0; i < 3; i++) at[t + i * 192] = g_attn[(size_t)blk * 576 + t + i * 192];
    __syncthreads();
    const int colbase = br * 192 + head * 24;
    const float* wrow = wproj + (size_t)t * CDIM + colbase;
    float* mrow = g_M + ((size_t)b * DIM + t) * CDIM + colbase;
#pragma unroll 4
    for (int d = 0; d < 24; d++) {
        float s = 0.f;
#pragma unroll
        for (int cc = 0; cc < 24; cc++) s = fmaf(wrow[cc], at[cc * 24 + d], s);
        mrow[d] = s;
    }
}

// ---------------- launch ----------------------------------------------------
extern "C" void kernel_launch(void* const* d_in, const int* in_sizes, int n_in,
                              void* d_out, int out_size) {
    const float* x       = (const float*)d_in[0];
    const float* w_qkv   = (const float*)d_in[1];
    const float* w_dw1   = (const float*)d_in[2];
    const float* w_dw2   = (const float*)d_in[3];
    const float* w_dw3   = (const float*)d_in[4];
    const float* w_proj  = (const float*)d_in[5];
    const float* temp    = (const float*)d_in[6];
    float* out = (float*)d_out;

    cudaFuncSetAttribute(k_mma_gemm<0>, cudaFuncAttributeMaxDynamicSharedMemorySize,
                         GEMM_SMEM_BYTES);
    cudaFuncSetAttribute(k_mma_gemm<1>, cudaFuncAttributeMaxDynamicSharedMemorySize,
                         GEMM_SMEM_BYTES);

    // qkv = W_qkv @ X : n-tiles 64, m-tiles ceil(576/128)=5, b=8
    k_mma_gemm<0><<<dim3(64, 5, NB), 256, GEMM_SMEM_BYTES>>>(w_qkv, x, nullptr);
    k_dwconv<<<(NB * CDIM * WIMG * (WIMG / 4)) / 256, 256>>>(w_dw1, w_dw2, w_dw3);
    k_gram<<<dim3(NBH, NSLICE), 64>>>();
    k_softmax<<<NBH, 576>>>(temp);
    k_buildM<<<NBH, 192>>>(w_proj);
    // out = M_b @ V_b : n-tiles 64, m-tiles 2, b=8
    k_mma_gemm<1><<<dim3(64, 2, NB), 256, GEMM_SMEM_BYTES>>>(nullptr, nullptr, out);
}

// round 5
// speedup vs baseline: 2.8522x; 1.2706x over previous
#include <cuda_runtime.h>
#include <cuda_fp16.h>
#include <cstdint>
#include <cstddef>

#define HW     16384
#define WIMG   128
#define DIM    192
#define CDIM   576
#define NB     8
#define NHEAD  8
#define NBH    192      // NB * 3 * NHEAD
#define NSLICE 16

// ---------------- scratch (device globals; no allocations allowed) ----------
__device__ __half g_qkvh [NB*CDIM*HW];
__device__ __half g_conv0h[NB*CDIM*HW];
__device__ __half g_conv1h[NB*CDIM*HW];
__device__ __half g_conv2h[NB*CDIM*HW];
__device__ float g_partS [NBH*NSLICE*24*24];
__device__ float g_partQQ[NBH*NSLICE*24];
__device__ float g_partKK[NBH*NSLICE*24];
__device__ float g_attn [NBH*24*24];
__device__ float g_M    [NB*DIM*CDIM];

// ======================= helpers ============================================
__device__ __forceinline__ uint32_t pack2(float a, float b) {
    __half2 h = __floats2half2_rn(a, b);     // lo = a, hi = b
    return *reinterpret_cast<uint32_t*>(&h);
}
__device__ __forceinline__ void mma_f16(float d[4], const uint32_t a[4],
                                        uint32_t b0, uint32_t b1) {
    asm volatile(
        "mma.sync.aligned.m16n8k16.row.col.f32.f16.f16.f32 "
        "{%0,%1,%2,%3}, {%4,%5,%6,%7}, {%8,%9}, {%0,%1,%2,%3};"
        : "+f"(d[0]), "+f"(d[1]), "+f"(d[2]), "+f"(d[3])
        : "r"(a[0]), "r"(a[1]), "r"(a[2]), "r"(a[3]), "r"(b0), "r"(b1));
}

// ======================= tensor GEMM (mma.sync f16, fp32 acc) ===============
// MODE 0: g_qkvh[b,576,HW](fp16) = W_qkv[576,192] @ X[b,192,HW]
// MODE 1: out[b,192,HW](fp32)    = g_M[b,192,576] @ V[b,576,HW] (V fp16, conv v-halves)
// CTA: 256 thr (8 warps 2x4), tile M128 x N256, K chunks of 32, double buffer.
#define AS_U32 20                 // 16 data u32 (32 halfs) + 4 pad
#define BS_U32 264                // 256 data u32 + 8 pad, per k-pair row
#define AS_BUF (128 * AS_U32)     // 2560 u32
#define BS_BUF (16 * BS_U32)      // 4224 u32
#define GEMM_SMEM_BYTES (2 * (AS_BUF + BS_BUF) * 4)   // 54272 B

template <int MODE>
__global__ __launch_bounds__(256, 1) void k_mma_gemm(const float* __restrict__ Amat,
                                                     const float* __restrict__ Xin,
                                                     float* __restrict__ Cout) {
    constexpr int KTOT = MODE ? CDIM : DIM;   // 576 / 192
    constexpr int NC   = KTOT / 32;           // 18 / 6
    constexpr int MLIM = MODE ? DIM : CDIM;   // 192 / 576

    extern __shared__ uint32_t smu[];

    const int tid = threadIdx.x;
    const int m0  = blockIdx.x * 128;
    const int n0  = blockIdx.y * 256;
    const int b   = blockIdx.z;

    const int warp = tid >> 5, lane = tid & 31;
    const int gid = lane >> 2, tg = lane & 3;
    const int m_w = (warp >> 2) * 64;
    const int n_w = (warp & 3) * 64;

    const float* Arow = MODE ? (g_M + (size_t)b * DIM * CDIM) : Amat;

    float4 pa[4];
    float4 pb0[4], pb1[4];     // MODE 0
    uint2  pc0[4], pc1[4];     // MODE 1

    auto pref = [&](int cc) {
        const int k0 = cc * 32;
#pragma unroll
        for (int i = 0; i < 4; i++) {
            int tsk = tid + (i << 8);
            int row = tsk >> 3, seg = tsk & 7;
            int mg = m0 + row;
            pa[i] = (mg < MLIM)
                ? *(const float4*)(Arow + (size_t)mg * KTOT + k0 + seg * 4)
                : make_float4(0.f, 0.f, 0.f, 0.f);
        }
#pragma unroll
        for (int i = 0; i < 4; i++) {
            int tsk = tid + (i << 8);
            int kp = tsk >> 6, seg = tsk & 63;
            int kg = k0 + 2 * kp;
            if (MODE == 0) {
                const float* p = Xin + ((size_t)(b * DIM + kg)) * HW + n0 + seg * 4;
                pb0[i] = *(const float4*)p;
                pb1[i] = *(const float4*)(p + HW);
            } else {
                int br = (kg >= 384) ? 2 : (kg >= 192) ? 1 : 0;
                int ch = kg - br * 192;
                const __half* cv = (br == 0) ? g_conv0h : (br == 1) ? g_conv1h : g_conv2h;
                const __half* p = cv + ((size_t)(b * CDIM + 384 + ch)) * HW + n0 + seg * 4;
                pc0[i] = *(const uint2*)p;
                pc1[i] = *(const uint2*)(p + HW);
            }
        }
    };
    auto sts = [&](int cc) {
        uint32_t* As = smu + (cc & 1) * AS_BUF;
        uint32_t* Bs = smu + 2 * AS_BUF + (cc & 1) * BS_BUF;
#pragma unroll
        for (int i = 0; i < 4; i++) {
            int tsk = tid + (i << 8);
            int row = tsk >> 3, seg = tsk & 7;
            As[row * AS_U32 + seg * 2]     = pack2(pa[i].x, pa[i].y);
            As[row * AS_U32 + seg * 2 + 1] = pack2(pa[i].z, pa[i].w);
        }
#pragma unroll
        for (int i = 0; i < 4; i++) {
            int tsk = tid + (i << 8);
            int kp = tsk >> 6, seg = tsk & 63;
            uint4 u;
            if (MODE == 0) {
                u.x = pack2(pb0[i].x, pb1[i].x);
                u.y = pack2(pb0[i].y, pb1[i].y);
                u.z = pack2(pb0[i].z, pb1[i].z);
                u.w = pack2(pb0[i].w, pb1[i].w);
            } else {
                u.x = __byte_perm(pc0[i].x, pc1[i].x, 0x5410);
                u.y = __byte_perm(pc0[i].x, pc1[i].x, 0x7632);
                u.z = __byte_perm(pc0[i].y, pc1[i].y, 0x5410);
                u.w = __byte_perm(pc0[i].y, pc1[i].y, 0x7632);
            }
            *(uint4*)&Bs[kp * BS_U32 + seg * 4] = u;
        }
    };

    float acc[4][8][4];
#pragma unroll
    for (int mt = 0; mt < 4; mt++)
#pragma unroll
        for (int nt = 0; nt < 8; nt++)
#pragma unroll
            for (int r = 0; r < 4; r++) acc[mt][nt][r] = 0.f;

    pref(0);
    sts(0);
    __syncthreads();

#pragma unroll 1
    for (int cc = 0; cc < NC; cc++) {
        if (cc + 1 < NC) pref(cc + 1);
        const uint32_t* As = smu + (cc & 1) * AS_BUF;
        const uint32_t* Bs = smu + 2 * AS_BUF + (cc & 1) * BS_BUF;
#pragma unroll
        for (int k16 = 0; k16 < 2; k16++) {
            uint32_t a[4][4];
#pragma unroll
            for (int mt = 0; mt < 4; mt++) {
                int ar = (m_w + mt * 16 + gid) * AS_U32 + k16 * 8 + tg;
                a[mt][0] = As[ar];
                a[mt][1] = As[ar + 8 * AS_U32];
                a[mt][2] = As[ar + 4];
                a[mt][3] = As[ar + 8 * AS_U32 + 4];
            }
#pragma unroll
            for (int nt = 0; nt < 8; nt++) {
                int col = n_w + nt * 8 + gid;
                uint32_t b0 = Bs[(k16 * 8 + tg) * BS_U32 + col];
                uint32_t b1 = Bs[(k16 * 8 + 4 + tg) * BS_U32 + col];
#pragma unroll
                for (int mt = 0; mt < 4; mt++)
                    mma_f16(acc[mt][nt], a[mt], b0, b1);
            }
        }
        __syncthreads();
        if (cc + 1 < NC) {
            sts(cc + 1);
            __syncthreads();
        }
    }

    // ------ epilogue ------
    if (MODE == 0) {
        __half* Cb = g_qkvh + (size_t)b * CDIM * HW;
#pragma unroll
        for (int mt = 0; mt < 4; mt++) {
            int r0 = m0 + m_w + mt * 16 + gid;
            int r1 = r0 + 8;
#pragma unroll
            for (int nt = 0; nt < 8; nt++) {
                int n = n0 + n_w + nt * 8 + tg * 2;
                if (r0 < MLIM)
                    *(uint32_t*)(Cb + (size_t)r0 * HW + n) = pack2(acc[mt][nt][0], acc[mt][nt][1]);
                if (r1 < MLIM)
                    *(uint32_t*)(Cb + (size_t)r1 * HW + n) = pack2(acc[mt][nt][2], acc[mt][nt][3]);
            }
        }
    } else {
        float* Cb = Cout + (size_t)b * DIM * HW;
#pragma unroll
        for (int mt = 0; mt < 4; mt++) {
            int r0 = m0 + m_w + mt * 16 + gid;
            int r1 = r0 + 8;
#pragma unroll
            for (int nt = 0; nt < 8; nt++) {
                int n = n0 + n_w + nt * 8 + tg * 2;
                if (r0 < MLIM)
                    *(float2*)(Cb + (size_t)r0 * HW + n) = make_float2(acc[mt][nt][0], acc[mt][nt][1]);
                if (r1 < MLIM)
                    *(float2*)(Cb + (size_t)r1 * HW + n) = make_float2(acc[mt][nt][2], acc[mt][nt][3]);
            }
        }
    }
}

// ---------------- fused depthwise 3x3, dilations 1/2/3 (fp16 I/O) -----------
__device__ __forceinline__ void unp4(uint2 u, float* d) {
    float2 f0 = __half22float2(*reinterpret_cast<__half2*>(&u.x));
    float2 f1 = __half22float2(*reinterpret_cast<__half2*>(&u.y));
    d[0] = f0.x; d[1] = f0.y; d[2] = f1.x; d[3] = f1.y;
}
template <int D>
__device__ __forceinline__ void conv3x3_d(const float v[7][12],
                                          const float* __restrict__ w, float o[4]) {
    float wr[9];
#pragma unroll
    for (int i = 0; i < 9; i++) wr[i] = __ldg(w + i);
#pragma unroll
    for (int x = 0; x < 4; x++) {
        float s = 0.f;
#pragma unroll
        for (int ky = 0; ky < 3; ky++)
#pragma unroll
            for (int kx = 0; kx < 3; kx++)
                s = fmaf(v[3 + (ky - 1) * D][4 + x + (kx - 1) * D], wr[ky * 3 + kx], s);
        o[x] = s;
    }
}

__global__ __launch_bounds__(256) void k_dwconv(const float* __restrict__ w1,
                                                const float* __restrict__ w2,
                                                const float* __restrict__ w3) {
    int gid = blockIdx.x * 256 + threadIdx.x;
    int xg = gid & 31;
    int y  = (gid >> 5) & 127;
    int bc = gid >> 12;
    int ch = bc % CDIM;
    const __half* in = g_qkvh + (size_t)bc * HW;
    int x0 = xg << 2;

    float v[7][12];
#pragma unroll
    for (int r = 0; r < 7; r++) {
        int yy = y + r - 3;
        if (yy < 0 || yy > 127) {
#pragma unroll
            for (int j = 0; j < 12; j++) v[r][j] = 0.f;
        } else {
            const __half* rp = in + yy * WIMG + x0;
            uint2 z = make_uint2(0u, 0u);
            uint2 u0 = (x0 == 0)   ? z : *(const uint2*)(rp - 4);
            uint2 u1 = *(const uint2*)rp;
            uint2 u2 = (x0 == 124) ? z : *(const uint2*)(rp + 4);
            unp4(u0, &v[r][0]);
            unp4(u1, &v[r][4]);
            unp4(u2, &v[r][8]);
        }
    }
    size_t obase = (size_t)bc * HW + y * WIMG + x0;
    float o[4];
    uint2 w;
    conv3x3_d<1>(v, w1 + ch * 9, o);
    w.x = pack2(o[0], o[1]); w.y = pack2(o[2], o[3]);
    *(uint2*)(g_conv0h + obase) = w;
    conv3x3_d<2>(v, w2 + ch * 9, o);
    w.x = pack2(o[0], o[1]); w.y = pack2(o[2], o[3]);
    *(uint2*)(g_conv1h + obase) = w;
    conv3x3_d<3>(v, w3 + ch * 9, o);
    w.x = pack2(o[0], o[1]); w.y = pack2(o[2], o[3]);
    *(uint2*)(g_conv2h + obase) = w;
}

// ---------------- Gram Q·K^T + norms, split-K (fp16 in) ----------------------
__global__ __launch_bounds__(64) void k_gram() {
    const int bh = blockIdx.x;
    const int slice = blockIdx.y;
    const int b = bh / 24, rem = bh % 24;
    const int br = rem >> 3, head = rem & 7;
    const __half* conv = (br == 0) ? g_conv0h : (br == 1) ? g_conv1h : g_conv2h;
    const __half* qb = conv + (size_t)(b * CDIM + head * 24) * HW;
    const __half* kb = conv + (size_t)(b * CDIM + 192 + head * 24) * HW;

    __shared__ __align__(16) float qs[24 * 130];
    __shared__ __align__(16) float ks[24 * 130];

    const int tid = threadIdx.x;
    const int rg = tid >> 3, cg = tid & 7;
    float acc[3][3] = {};
    float qq[3] = {}, kk[3] = {};
    const int n0s = slice * 1024;

    for (int cch = 0; cch < 8; cch++) {
        const int n0 = n0s + cch * 128;
#pragma unroll
        for (int i = 0; i < 12; i++) {
            int idx = (i << 6) + tid;
            int row = idx >> 5, c4 = (idx & 31) << 2;
            uint2 qu = *(const uint2*)(qb + (size_t)row * HW + n0 + c4);
            uint2 ku = *(const uint2*)(kb + (size_t)row * HW + n0 + c4);
            unp4(qu, &qs[row * 130 + c4]);
            unp4(ku, &ks[row * 130 + c4]);
        }
        __syncthreads();
#pragma unroll 4
        for (int n = 0; n < 128; n += 2) {
            float2 qv[3], kv[3];
#pragma unroll
            for (int i = 0; i < 3; i++) {
                qv[i] = *(float2*)&qs[(rg * 3 + i) * 130 + n];
                kv[i] = *(float2*)&ks[(cg * 3 + i) * 130 + n];
            }
#pragma unroll
            for (int i = 0; i < 3; i++)
#pragma unroll
                for (int j = 0; j < 3; j++)
                    acc[i][j] += qv[i].x * kv[j].x + qv[i].y * kv[j].y;
            if (cg == 0) {
#pragma unroll
                for (int i = 0; i < 3; i++)
                    qq[i] += qv[i].x * qv[i].x + qv[i].y * qv[i].y;
            }
            if (rg == 0) {
#pragma unroll
                for (int j = 0; j < 3; j++)
                    kk[j] += kv[j].x * kv[j].x + kv[j].y * kv[j].y;
            }
        }
        __syncthreads();
    }
    const int base = (bh * NSLICE + slice) * 24;
#pragma unroll
    for (int i = 0; i < 3; i++)
#pragma unroll
        for (int j = 0; j < 3; j++)
            g_partS[(size_t)(base + rg * 3 + i) * 24 + cg * 3 + j] = acc[i][j];
    if (cg == 0)
#pragma unroll
        for (int i = 0; i < 3; i++) g_partQQ[base + rg * 3 + i] = qq[i];
    if (rg == 0)
#pragma unroll
        for (int j = 0; j < 3; j++) g_partKK[base + cg * 3 + j] = kk[j];
}

// ---------------- reduce, normalize, temperature, softmax --------------------
__global__ __launch_bounds__(576) void k_softmax(const float* __restrict__ temperature) {
    const int bh = blockIdx.x;
    const int head = bh & 7;
    const int t = threadIdx.x;
    const int c = t / 24, d = t % 24;

    float s = 0.f;
    for (int sl = 0; sl < NSLICE; sl++)
        s += g_partS[(size_t)((bh * NSLICE + sl) * 24 + c) * 24 + d];

    __shared__ float nq[24], nk[24], logits[576], rmax[24], rsum[24];
    if (t < 24) {
        float a = 0.f, b2 = 0.f;
        for (int sl = 0; sl < NSLICE; sl++) {
            a  += g_partQQ[(bh * NSLICE + sl) * 24 + t];
            b2 += g_partKK[(bh * NSLICE + sl) * 24 + t];
        }
        nq[t] = fmaxf(sqrtf(a),  1e-12f);
        nk[t] = fmaxf(sqrtf(b2), 1e-12f);
    }
    __syncthreads();
    float lg = s / (nq[c] * nk[d]) * temperature[head];
    logits[t] = lg;
    __syncthreads();
    if (d == 0) {
        float mx = -1e30f;
        for (int j = 0; j < 24; j++) mx = fmaxf(mx, logits[c * 24 + j]);
        float sm = 0.f;
        for (int j = 0; j < 24; j++) sm += expf(logits[c * 24 + j] - mx);
        rmax[c] = mx; rsum[c] = sm;
    }
    __syncthreads();
    g_attn[(size_t)bh * 576 + t] = expf(lg - rmax[c]) / rsum[c];
}

// ---------------- fold proj into attn: M[b,o,col] ----------------------------
__global__ __launch_bounds__(192) void k_buildM(const float* __restrict__ wproj) {
    const int blk = blockIdx.x;
    const int b = blk / 24, rem = blk % 24;
    const int br = rem >> 3, head = rem & 7;
    __shared__ float at[576];
    const int t = threadIdx.x;
#pragma unroll
    for (int i = 0; i < 3; i++) at[t + i * 192] = g_attn[(size_t)blk * 576 + t + i * 192];
    __syncthreads();
    const int colbase = br * 192 + head * 24;
    const float* wrow = wproj + (size_t)t * CDIM + colbase;
    float* mrow = g_M + ((size_t)b * DIM + t) * CDIM + colbase;
#pragma unroll 4
    for (int d = 0; d < 24; d++) {
        float s = 0.f;
#pragma unroll
        for (int cc = 0; cc < 24; cc++) s = fmaf(wrow[cc], at[cc * 24 + d], s);
        mrow[d] = s;
    }
}

// ---------------- launch ----------------------------------------------------
extern "C" void kernel_launch(void* const* d_in, const int* in_sizes, int n_in,
                              void* d_out, int out_size) {
    const float* x       = (const float*)d_in[0];
    const float* w_qkv   = (const float*)d_in[1];
    const float* w_dw1   = (const float*)d_in[2];
    const float* w_dw2   = (const float*)d_in[3];
    const float* w_dw3   = (const float*)d_in[4];
    const float* w_proj  = (const float*)d_in[5];
    const float* temp    = (const float*)d_in[6];
    float* out = (float*)d_out;

    cudaFuncSetAttribute(k_mma_gemm<0>, cudaFuncAttributeMaxDynamicSharedMemorySize,
                         GEMM_SMEM_BYTES);
    cudaFuncSetAttribute(k_mma_gemm<1>, cudaFuncAttributeMaxDynamicSharedMemorySize,
                         GEMM_SMEM_BYTES);

    // qkv = W_qkv @ X : grid.x = m-tiles (L2 reuse of B across m), y = n-tiles
    k_mma_gemm<0><<<dim3(5, 64, NB), 256, GEMM_SMEM_BYTES>>>(w_qkv, x, nullptr);
    k_dwconv<<<(NB * CDIM * WIMG * (WIMG / 4)) / 256, 256>>>(w_dw1, w_dw2, w_dw3);
    k_gram<<<dim3(NBH, NSLICE), 64>>>();
    k_softmax<<<NBH, 576>>>(temp);
    k_buildM<<<NBH, 192>>>(w_proj);
    // out = M_b @ V_b
    k_mma_gemm<1><<<dim3(2, 64, NB), 256, GEMM_SMEM_BYTES>>>(nullptr, nullptr, out);
}

// round 7
// speedup vs baseline: 2.8645x; 1.0043x over previous
#include <cuda_runtime.h>
#include <cuda_fp16.h>
#include <cstdint>
#include <cstddef>

#define HW     16384
#define WIMG   128
#define DIM    192
#define CDIM   576
#define NB     8
#define NHEAD  8
#define NBH    192      // NB * 3 * NHEAD
#define NSLICE 16

// ---------------- scratch (device globals; no allocations allowed) ----------
__device__ __half g_xh   [NB*DIM*HW];      // fp16 copy of input X
__device__ __half g_wqkvh[CDIM*DIM];       // fp16 copy of W_qkv
__device__ __half g_qkvh [NB*CDIM*HW];
__device__ __half g_conv0h[NB*CDIM*HW];
__device__ __half g_conv1h[NB*CDIM*HW];
__device__ __half g_conv2h[NB*CDIM*HW];
__device__ float g_partS [NBH*NSLICE*24*24];
__device__ float g_partQQ[NBH*NSLICE*24];
__device__ float g_partKK[NBH*NSLICE*24];
__device__ float g_attn [NBH*24*24];
__device__ __half g_Mh  [NB*DIM*CDIM];

// ======================= helpers ============================================
__device__ __forceinline__ uint32_t smem_u32(const void* p) {
    uint32_t a;
    asm("{ .reg .u64 t; cvta.to.shared.u64 t, %1; cvt.u32.u64 %0, t; }"
        : "=r"(a) : "l"(p));
    return a;
}
__device__ __forceinline__ void cp_async16(uint32_t dst, const void* src, int src_sz) {
    asm volatile("cp.async.ca.shared.global [%0], [%1], 16, %2;"
                 :: "r"(dst), "l"(src), "r"(src_sz));
}
#define CP_COMMIT()  asm volatile("cp.async.commit_group;" ::: "memory")
#define CP_WAIT(n)   asm volatile("cp.async.wait_group %0;" :: "n"(n) : "memory")

__device__ __forceinline__ uint32_t pack2(float a, float b) {
    __half2 h = __floats2half2_rn(a, b);
    return *reinterpret_cast<uint32_t*>(&h);
}
__device__ __forceinline__ void mma_f16(float d[4], const uint32_t a[4],
                                        uint32_t b0, uint32_t b1) {
    asm volatile(
        "mma.sync.aligned.m16n8k16.row.col.f32.f16.f16.f32 "
        "{%0,%1,%2,%3}, {%4,%5,%6,%7}, {%8,%9}, {%0,%1,%2,%3};"
        : "+f"(d[0]), "+f"(d[1]), "+f"(d[2]), "+f"(d[3])
        : "r"(a[0]), "r"(a[1]), "r"(a[2]), "r"(a[3]), "r"(b0), "r"(b1));
}
__device__ __forceinline__ void ldmatrix_x4(uint32_t r[4], uint32_t addr) {
    asm volatile("ldmatrix.sync.aligned.m8n8.x4.shared.b16 {%0,%1,%2,%3}, [%4];"
                 : "=r"(r[0]), "=r"(r[1]), "=r"(r[2]), "=r"(r[3]) : "r"(addr));
}
__device__ __forceinline__ void ldmatrix_x2t(uint32_t& b0, uint32_t& b1, uint32_t addr) {
    asm volatile("ldmatrix.sync.aligned.m8n8.x2.trans.shared.b16 {%0,%1}, [%2];"
                 : "=r"(b0), "=r"(b1) : "r"(addr));
}

// ======================= fp16 conversion prep ================================
__global__ __launch_bounds__(256) void k_cvt(const float4* __restrict__ src,
                                             uint2* __restrict__ dst) {
    int i = blockIdx.x * 256 + threadIdx.x;
    float4 v = src[i];
    dst[i] = make_uint2(pack2(v.x, v.y), pack2(v.z, v.w));
}

// ======================= tensor GEMM (cp.async + ldmatrix + mma f16) ========
// MODE 0: g_qkvh[b,576,HW](fp16) = g_wqkvh[576,192] @ g_xh[b,192,HW]
// MODE 1: out[b,192,HW](fp32)    = g_Mh[b,192,576] @ V[b,576,HW] (conv v-halves)
// CTA: 256 thr (8 warps 2x4), tile M128 x N256, K chunks of 32, 3-stage pipe.
// A smem: [128 m][32 k] fp16, row stride 80B  -> ldmatrix x4 conflict-free
// B smem: [32 k][256 n] fp16, row stride 528B -> ldmatrix x2.trans conflict-free
#define A_BUF_B 10240     // 128*80
#define B_BUF_B 16896     // 32*528
#define GEMM_SMEM_BYTES (3 * (A_BUF_B + B_BUF_B))   // 81408

template <int MODE>
__global__ __launch_bounds__(256, 1) void k_mma_gemm(float* __restrict__ Cout) {
    constexpr int KTOT = MODE ? CDIM : DIM;   // 576 / 192
    constexpr int NC   = KTOT / 32;           // 18 / 6
    constexpr int MLIM = MODE ? DIM : CDIM;   // 192 / 576

    extern __shared__ __align__(16) char smc[];
    const uint32_t sb = smem_u32(smc);

    const int tid = threadIdx.x;
    const int m0  = blockIdx.x * 128;
    const int n0  = blockIdx.y * 256;
    const int b   = blockIdx.z;

    const int warp = tid >> 5, lane = tid & 31;
    const int gid = lane >> 2, tg = lane & 3;
    const int m_w = (warp >> 2) * 64;
    const int n_w = (warp & 3) * 64;

    const __half* Aptr = MODE ? (g_Mh + (size_t)b * DIM * CDIM) : g_wqkvh;

    auto fill = [&](int cc) {
        const int k0 = cc * 32;
        const uint32_t aB = sb + (cc % 3) * A_BUF_B;
        const uint32_t bB = sb + 3 * A_BUF_B + (cc % 3) * B_BUF_B;
        // A: 128 rows x 4 chunks of 16B
#pragma unroll
        for (int i = 0; i < 2; i++) {
            int tsk = tid + (i << 8);
            int row = tsk >> 2, seg = tsk & 3;
            int mg = m0 + row;
            bool ok = (mg < MLIM);
            const __half* src = Aptr + (size_t)(ok ? mg : 0) * KTOT + k0 + seg * 8;
            cp_async16(aB + row * 80 + seg * 16, src, ok ? 16 : 0);
        }
        // B: 32 k rows x 32 chunks of 16B
#pragma unroll
        for (int i = 0; i < 4; i++) {
            int tsk = tid + (i << 8);
            int row = tsk >> 5, seg = tsk & 31;
            int kg = k0 + row;
            const __half* src;
            if (MODE == 0) {
                src = g_xh + ((size_t)(b * DIM + kg)) * HW + n0 + seg * 8;
            } else {
                int br = (kg >= 384) ? 2 : (kg >= 192) ? 1 : 0;
                int ch = kg - br * 192;
                const __half* cv = (br == 0) ? g_conv0h : (br == 1) ? g_conv1h : g_conv2h;
                src = cv + ((size_t)(b * CDIM + 384 + ch)) * HW + n0 + seg * 8;
            }
            cp_async16(bB + row * 528 + seg * 16, src, 16);
        }
    };

    float acc[4][8][4];
#pragma unroll
    for (int mt = 0; mt < 4; mt++)
#pragma unroll
        for (int nt = 0; nt < 8; nt++)
#pragma unroll
            for (int r = 0; r < 4; r++) acc[mt][nt][r] = 0.f;

    fill(0); CP_COMMIT();
    fill(1); CP_COMMIT();

#pragma unroll 1
    for (int cc = 0; cc < NC; cc++) {
        if (cc + 1 < NC) { CP_WAIT(1); } else { CP_WAIT(0); }
        __syncthreads();
        if (cc + 2 < NC) { fill(cc + 2); CP_COMMIT(); }

        const uint32_t aB = sb + (cc % 3) * A_BUF_B;
        const uint32_t bB = sb + 3 * A_BUF_B + (cc % 3) * B_BUF_B;
#pragma unroll
        for (int k16 = 0; k16 < 2; k16++) {
            uint32_t a[4][4];
#pragma unroll
            for (int mt = 0; mt < 4; mt++) {
                uint32_t addr = aB + (m_w + mt * 16 + (lane & 15)) * 80
                              + k16 * 32 + ((lane >> 4) & 1) * 16;
                ldmatrix_x4(a[mt], addr);
            }
#pragma unroll
            for (int nt = 0; nt < 8; nt++) {
                uint32_t b0, b1;
                uint32_t baddr = bB + (k16 * 16 + (lane & 15)) * 528
                               + (n_w + nt * 8) * 2;
                ldmatrix_x2t(b0, b1, baddr);
#pragma unroll
                for (int mt = 0; mt < 4; mt++)
                    mma_f16(acc[mt][nt], a[mt], b0, b1);
            }
        }
    }

    // ------ epilogue ------
    if (MODE == 0) {
        __half* Cb = g_qkvh + (size_t)b * CDIM * HW;
#pragma unroll
        for (int mt = 0; mt < 4; mt++) {
            int r0 = m0 + m_w + mt * 16 + gid;
            int r1 = r0 + 8;
#pragma unroll
            for (int nt = 0; nt < 8; nt++) {
                int n = n0 + n_w + nt * 8 + tg * 2;
                if (r0 < MLIM)
                    *(uint32_t*)(Cb + (size_t)r0 * HW + n) = pack2(acc[mt][nt][0], acc[mt][nt][1]);
                if (r1 < MLIM)
                    *(uint32_t*)(Cb + (size_t)r1 * HW + n) = pack2(acc[mt][nt][2], acc[mt][nt][3]);
            }
        }
    } else {
        float* Cb = Cout + (size_t)b * DIM * HW;
#pragma unroll
        for (int mt = 0; mt < 4; mt++) {
            int r0 = m0 + m_w + mt * 16 + gid;
            int r1 = r0 + 8;
#pragma unroll
            for (int nt = 0; nt < 8; nt++) {
                int n = n0 + n_w + nt * 8 + tg * 2;
                if (r0 < MLIM)
                    *(float2*)(Cb + (size_t)r0 * HW + n) = make_float2(acc[mt][nt][0], acc[mt][nt][1]);
                if (r1 < MLIM)
                    *(float2*)(Cb + (size_t)r1 * HW + n) = make_float2(acc[mt][nt][2], acc[mt][nt][3]);
            }
        }
    }
}

// ---------------- fused depthwise 3x3, dilations 1/2/3 (fp16 I/O) -----------
__device__ __forceinline__ void unp4(uint2 u, float* d) {
    float2 f0 = __half22float2(*reinterpret_cast<__half2*>(&u.x));
    float2 f1 = __half22float2(*reinterpret_cast<__half2*>(&u.y));
    d[0] = f0.x; d[1] = f0.y; d[2] = f1.x; d[3] = f1.y;
}
template <int D>
__device__ __forceinline__ void conv3x3_d(const float v[7][12],
                                          const float* __restrict__ w, float o[4]) {
    float wr[9];
#pragma unroll
    for (int i = 0; i < 9; i++) wr[i] = __ldg(w + i);
#pragma unroll
    for (int x = 0; x < 4; x++) {
        float s = 0.f;
#pragma unroll
        for (int ky = 0; ky < 3; ky++)
#pragma unroll
            for (int kx = 0; kx < 3; kx++)
                s = fmaf(v[3 + (ky - 1) * D][4 + x + (kx - 1) * D], wr[ky * 3 + kx], s);
        o[x] = s;
    }
}

__global__ __launch_bounds__(256) void k_dwconv(const float* __restrict__ w1,
                                                const float* __restrict__ w2,
                                                const float* __restrict__ w3) {
    int gid = blockIdx.x * 256 + threadIdx.x;
    int xg = gid & 31;
    int y  = (gid >> 5) & 127;
    int bc = gid >> 12;
    int ch = bc % CDIM;
    const __half* in = g_qkvh + (size_t)bc * HW;
    int x0 = xg << 2;

    float v[7][12];
#pragma unroll
    for (int r = 0; r < 7; r++) {
        int yy = y + r - 3;
        if (yy < 0 || yy > 127) {
#pragma unroll
            for (int j = 0; j < 12; j++) v[r][j] = 0.f;
        } else {
            const __half* rp = in + yy * WIMG + x0;
            uint2 z = make_uint2(0u, 0u);
            uint2 u0 = (x0 == 0)   ? z : *(const uint2*)(rp - 4);
            uint2 u1 = *(const uint2*)rp;
            uint2 u2 = (x0 == 124) ? z : *(const uint2*)(rp + 4);
            unp4(u0, &v[r][0]);
            unp4(u1, &v[r][4]);
            unp4(u2, &v[r][8]);
        }
    }
    size_t obase = (size_t)bc * HW + y * WIMG + x0;
    float o[4];
    uint2 w;
    conv3x3_d<1>(v, w1 + ch * 9, o);
    w.x = pack2(o[0], o[1]); w.y = pack2(o[2], o[3]);
    *(uint2*)(g_conv0h + obase) = w;
    conv3x3_d<2>(v, w2 + ch * 9, o);
    w.x = pack2(o[0], o[1]); w.y = pack2(o[2], o[3]);
    *(uint2*)(g_conv1h + obase) = w;
    conv3x3_d<3>(v, w3 + ch * 9, o);
    w.x = pack2(o[0], o[1]); w.y = pack2(o[2], o[3]);
    *(uint2*)(g_conv2h + obase) = w;
}

// ---------------- Gram Q·K^T + norms, split-K (fp16 in) ----------------------
__global__ __launch_bounds__(64) void k_gram() {
    const int bh = blockIdx.x;
    const int slice = blockIdx.y;
    const int b = bh / 24, rem = bh % 24;
    const int br = rem >> 3, head = rem & 7;
    const __half* conv = (br == 0) ? g_conv0h : (br == 1) ? g_conv1h : g_conv2h;
    const __half* qb = conv + (size_t)(b * CDIM + head * 24) * HW;
    const __half* kb = conv + (size_t)(b * CDIM + 192 + head * 24) * HW;

    __shared__ __align__(16) float qs[24 * 130];
    __shared__ __align__(16) float ks[24 * 130];

    const int tid = threadIdx.x;
    const int rg = tid >> 3, cg = tid & 7;
    float acc[3][3] = {};
    float qq[3] = {}, kk[3] = {};
    const int n0s = slice * 1024;

    for (int cch = 0; cch < 8; cch++) {
        const int n0 = n0s + cch * 128;
#pragma unroll
        for (int i = 0; i < 12; i++) {
            int idx = (i << 6) + tid;
            int row = idx >> 5, c4 = (idx & 31) << 2;
            uint2 qu = *(const uint2*)(qb + (size_t)row * HW + n0 + c4);
            uint2 ku = *(const uint2*)(kb + (size_t)row * HW + n0 + c4);
            unp4(qu, &qs[row * 130 + c4]);
            unp4(ku, &ks[row * 130 + c4]);
        }
        __syncthreads();
#pragma unroll 4
        for (int n = 0; n < 128; n += 2) {
            float2 qv[3], kv[3];
#pragma unroll
            for (int i = 0; i < 3; i++) {
                qv[i] = *(float2*)&qs[(rg * 3 + i) * 130 + n];
                kv[i] = *(float2*)&ks[(cg * 3 + i) * 130 + n];
            }
#pragma unroll
            for (int i = 0; i < 3; i++)
#pragma unroll
                for (int j = 0; j < 3; j++)
                    acc[i][j] += qv[i].x * kv[j].x + qv[i].y * kv[j].y;
            if (cg == 0) {
#pragma unroll
                for (int i = 0; i < 3; i++)
                    qq[i] += qv[i].x * qv[i].x + qv[i].y * qv[i].y;
            }
            if (rg == 0) {
#pragma unroll
                for (int j = 0; j < 3; j++)
                    kk[j] += kv[j].x * kv[j].x + kv[j].y * kv[j].y;
            }
        }
        __syncthreads();
    }
    const int base = (bh * NSLICE + slice) * 24;
#pragma unroll
    for (int i = 0; i < 3; i++)
#pragma unroll
        for (int j = 0; j < 3; j++)
            g_partS[(size_t)(base + rg * 3 + i) * 24 + cg * 3 + j] = acc[i][j];
    if (cg == 0)
#pragma unroll
        for (int i = 0; i < 3; i++) g_partQQ[base + rg * 3 + i] = qq[i];
    if (rg == 0)
#pragma unroll
        for (int j = 0; j < 3; j++) g_partKK[base + cg * 3 + j] = kk[j];
}

// ---------------- reduce, normalize, temperature, softmax --------------------
__global__ __launch_bounds__(576) void k_softmax(const float* __restrict__ temperature) {
    const int bh = blockIdx.x;
    const int head = bh & 7;
    const int t = threadIdx.x;
    const int c = t / 24, d = t % 24;

    float s = 0.f;
    for (int sl = 0; sl < NSLICE; sl++)
        s += g_partS[(size_t)((bh * NSLICE + sl) * 24 + c) * 24 + d];

    __shared__ float nq[24], nk[24], logits[576], rmax[24], rsum[24];
    if (t < 24) {
        float a = 0.f, b2 = 0.f;
        for (int sl = 0; sl < NSLICE; sl++) {
            a  += g_partQQ[(bh * NSLICE + sl) * 24 + t];
            b2 += g_partKK[(bh * NSLICE + sl) * 24 + t];
        }
        nq[t] = fmaxf(sqrtf(a),  1e-12f);
        nk[t] = fmaxf(sqrtf(b2), 1e-12f);
    }
    __syncthreads();
    float lg = s / (nq[c] * nk[d]) * temperature[head];
    logits[t] = lg;
    __syncthreads();
    if (d == 0) {
        float mx = -1e30f;
        for (int j = 0; j < 24; j++) mx = fmaxf(mx, logits[c * 24 + j]);
        float sm = 0.f;
        for (int j = 0; j < 24; j++) sm += expf(logits[c * 24 + j] - mx);
        rmax[c] = mx; rsum[c] = sm;
    }
    __syncthreads();
    g_attn[(size_t)bh * 576 + t] = expf(lg - rmax[c]) / rsum[c];
}

// ---------------- fold proj into attn: M[b,o,col] (fp16 out) -----------------
__global__ __launch_bounds__(192) void k_buildM(const float* __restrict__ wproj) {
    const int blk = blockIdx.x;
    const int b = blk / 24, rem = blk % 24;
    const int br = rem >> 3, head = rem & 7;
    __shared__ float at[576];
    const int t = threadIdx.x;
#pragma unroll
    for (int i = 0; i < 3; i++) at[t + i * 192] = g_attn[(size_t)blk * 576 + t + i * 192];
    __syncthreads();
    const int colbase = br * 192 + head * 24;
    const float* wrow = wproj + (size_t)t * CDIM + colbase;
    __half* mrow = g_Mh + ((size_t)b * DIM + t) * CDIM + colbase;
#pragma unroll 4
    for (int d = 0; d < 24; d++) {
        float s = 0.f;
#pragma unroll
        for (int cc = 0; cc < 24; cc++) s = fmaf(wrow[cc], at[cc * 24 + d], s);
        mrow[d] = __float2half_rn(s);
    }
}

// ---------------- launch ----------------------------------------------------
extern "C" void kernel_launch(void* const* d_in, const int* in_sizes, int n_in,
                              void* d_out, int out_size) {
    const float* x       = (const float*)d_in[0];
    const float* w_qkv   = (const float*)d_in[1];
    const float* w_dw1   = (const float*)d_in[2];
    const float* w_dw2   = (const float*)d_in[3];
    const float* w_dw3   = (const float*)d_in[4];
    const float* w_proj  = (const float*)d_in[5];
    const float* temp    = (const float*)d_in[6];
    float* out = (float*)d_out;

    cudaFuncSetAttribute(k_mma_gemm<0>, cudaFuncAttributeMaxDynamicSharedMemorySize,
                         GEMM_SMEM_BYTES);
    cudaFuncSetAttribute(k_mma_gemm<1>, cudaFuncAttributeMaxDynamicSharedMemorySize,
                         GEMM_SMEM_BYTES);

    __half* d_xh;    cudaGetSymbolAddress((void**)&d_xh, g_xh);
    __half* d_wh;    cudaGetSymbolAddress((void**)&d_wh, g_wqkvh);

    // fp16 prep: X (25165824 elems /4 = 6291456 tasks), W_qkv (110592 /4 = 27648)
    k_cvt<<<24576, 256>>>((const float4*)x, (uint2*)d_xh);
    k_cvt<<<108, 256>>>((const float4*)w_qkv, (uint2*)d_wh);

    // qkv = W_qkv @ X : grid.x = m-tiles (L2 reuse of B across m), y = n-tiles
    k_mma_gemm<0><<<dim3(5, 64, NB), 256, GEMM_SMEM_BYTES>>>(nullptr);
    k_dwconv<<<(NB * CDIM * WIMG * (WIMG / 4)) / 256, 256>>>(w_dw1, w_dw2, w_dw3);
    k_gram<<<dim3(NBH, NSLICE), 64>>>();
    k_softmax<<<NBH, 576>>>(temp);
    k_buildM<<<NBH, 192>>>(w_proj);
    // out = M_b @ V_b
    k_mma_gemm<1><<<dim3(2, 64, NB), 256, GEMM_SMEM_BYTES>>>(out);
}

// round 9
// speedup vs baseline: 3.2241x; 1.1255x over previous
#include <cuda_runtime.h>
#include <cuda_fp16.h>
#include <cstdint>
#include <cstddef>

#define HW     16384
#define WIMG   128
#define DIM    192
#define CDIM   576
#define NB     8
#define NHEAD  8
#define NBH    192      // NB * 3 * NHEAD
#define NSLICE 16

// ---------------- scratch (device globals; no allocations allowed) ----------
__device__ __half g_xh   [NB*DIM*HW];      // fp16 copy of input X
__device__ __half g_wqkvh[CDIM*DIM];       // fp16 copy of W_qkv
__device__ __half g_qkvh [NB*CDIM*HW];
__device__ __half g_conv0h[NB*CDIM*HW];
__device__ __half g_conv1h[NB*CDIM*HW];
__device__ __half g_conv2h[NB*CDIM*HW];
__device__ float g_partS [NBH*NSLICE*24*24];
__device__ float g_partQQ[NBH*NSLICE*24];
__device__ float g_partKK[NBH*NSLICE*24];
__device__ float g_attn [NBH*24*24];
__device__ __half g_Mh  [NB*DIM*CDIM];

// ======================= helpers ============================================
__device__ __forceinline__ uint32_t smem_u32(const void* p) {
    uint32_t a;
    asm("{ .reg .u64 t; cvta.to.shared.u64 t, %1; cvt.u32.u64 %0, t; }"
        : "=r"(a) : "l"(p));
    return a;
}
__device__ __forceinline__ void cp_async16(uint32_t dst, const void* src, int src_sz) {
    asm volatile("cp.async.ca.shared.global [%0], [%1], 16, %2;"
                 :: "r"(dst), "l"(src), "r"(src_sz));
}
#define CP_COMMIT()  asm volatile("cp.async.commit_group;" ::: "memory")
#define CP_WAIT(n)   asm volatile("cp.async.wait_group %0;" :: "n"(n) : "memory")

__device__ __forceinline__ uint32_t pack2(float a, float b) {
    __half2 h = __floats2half2_rn(a, b);
    return *reinterpret_cast<uint32_t*>(&h);
}
__device__ __forceinline__ void mma_f16(float d[4], const uint32_t a[4],
                                        uint32_t b0, uint32_t b1) {
    asm volatile(
        "mma.sync.aligned.m16n8k16.row.col.f32.f16.f16.f32 "
        "{%0,%1,%2,%3}, {%4,%5,%6,%7}, {%8,%9}, {%0,%1,%2,%3};"
        : "+f"(d[0]), "+f"(d[1]), "+f"(d[2]), "+f"(d[3])
        : "r"(a[0]), "r"(a[1]), "r"(a[2]), "r"(a[3]), "r"(b0), "r"(b1));
}
__device__ __forceinline__ void ldmatrix_x4(uint32_t r[4], uint32_t addr) {
    asm volatile("ldmatrix.sync.aligned.m8n8.x4.shared.b16 {%0,%1,%2,%3}, [%4];"
                 : "=r"(r[0]), "=r"(r[1]), "=r"(r[2]), "=r"(r[3]) : "r"(addr));
}
__device__ __forceinline__ void ldmatrix_x2t(uint32_t& b0, uint32_t& b1, uint32_t addr) {
    asm volatile("ldmatrix.sync.aligned.m8n8.x2.trans.shared.b16 {%0,%1}, [%2];"
                 : "=r"(b0), "=r"(b1) : "r"(addr));
}
__device__ __forceinline__ void unp4(uint2 u, float* d) {
    float2 f0 = __half22float2(*reinterpret_cast<__half2*>(&u.x));
    float2 f1 = __half22float2(*reinterpret_cast<__half2*>(&u.y));
    d[0] = f0.x; d[1] = f0.y; d[2] = f1.x; d[3] = f1.y;
}

// ======================= fp16 conversion prep ================================
__global__ __launch_bounds__(256) void k_cvt(const float4* __restrict__ src,
                                             uint2* __restrict__ dst) {
    int i = blockIdx.x * 256 + threadIdx.x;
    float4 v = src[i];
    dst[i] = make_uint2(pack2(v.x, v.y), pack2(v.z, v.w));
}

// ======================= tensor GEMM (cp.async + ldmatrix + mma f16) ========
// MODE 0: g_qkvh[b,576,HW](fp16) = g_wqkvh[576,192] @ g_xh[b,192,HW]
// MODE 1: out[b,192,HW](fp32)    = g_Mh[b,192,576] @ V[b,576,HW] (conv v-halves)
#define A_BUF_B 10240     // 128*80
#define B_BUF_B 16896     // 32*528
#define GEMM_SMEM_BYTES (3 * (A_BUF_B + B_BUF_B))   // 81408

template <int MODE>
__global__ __launch_bounds__(256, 1) void k_mma_gemm(float* __restrict__ Cout) {
    constexpr int KTOT = MODE ? CDIM : DIM;
    constexpr int NC   = KTOT / 32;
    constexpr int MLIM = MODE ? DIM : CDIM;

    extern __shared__ __align__(16) char smc[];
    const uint32_t sb = smem_u32(smc);

    const int tid = threadIdx.x;
    const int m0  = blockIdx.x * 128;
    const int n0  = blockIdx.y * 256;
    const int b   = blockIdx.z;

    const int warp = tid >> 5, lane = tid & 31;
    const int gid = lane >> 2, tg = lane & 3;
    const int m_w = (warp >> 2) * 64;
    const int n_w = (warp & 3) * 64;

    const __half* Aptr = MODE ? (g_Mh + (size_t)b * DIM * CDIM) : g_wqkvh;

    auto fill = [&](int cc) {
        const int k0 = cc * 32;
        const uint32_t aB = sb + (cc % 3) * A_BUF_B;
        const uint32_t bB = sb + 3 * A_BUF_B + (cc % 3) * B_BUF_B;
#pragma unroll
        for (int i = 0; i < 2; i++) {
            int tsk = tid + (i << 8);
            int row = tsk >> 2, seg = tsk & 3;
            int mg = m0 + row;
            bool ok = (mg < MLIM);
            const __half* src = Aptr + (size_t)(ok ? mg : 0) * KTOT + k0 + seg * 8;
            cp_async16(aB + row * 80 + seg * 16, src, ok ? 16 : 0);
        }
#pragma unroll
        for (int i = 0; i < 4; i++) {
            int tsk = tid + (i << 8);
            int row = tsk >> 5, seg = tsk & 31;
            int kg = k0 + row;
            const __half* src;
            if (MODE == 0) {
                src = g_xh + ((size_t)(b * DIM + kg)) * HW + n0 + seg * 8;
            } else {
                int br = (kg >= 384) ? 2 : (kg >= 192) ? 1 : 0;
                int ch = kg - br * 192;
                const __half* cv = (br == 0) ? g_conv0h : (br == 1) ? g_conv1h : g_conv2h;
                src = cv + ((size_t)(b * CDIM + 384 + ch)) * HW + n0 + seg * 8;
            }
            cp_async16(bB + row * 528 + seg * 16, src, 16);
        }
    };

    float acc[4][8][4];
#pragma unroll
    for (int mt = 0; mt < 4; mt++)
#pragma unroll
        for (int nt = 0; nt < 8; nt++)
#pragma unroll
            for (int r = 0; r < 4; r++) acc[mt][nt][r] = 0.f;

    fill(0); CP_COMMIT();
    fill(1); CP_COMMIT();

#pragma unroll 1
    for (int cc = 0; cc < NC; cc++) {
        if (cc + 1 < NC) { CP_WAIT(1); } else { CP_WAIT(0); }
        __syncthreads();
        if (cc + 2 < NC) { fill(cc + 2); CP_COMMIT(); }

        const uint32_t aB = sb + (cc % 3) * A_BUF_B;
        const uint32_t bB = sb + 3 * A_BUF_B + (cc % 3) * B_BUF_B;
#pragma unroll
        for (int k16 = 0; k16 < 2; k16++) {
            uint32_t a[4][4];
#pragma unroll
            for (int mt = 0; mt < 4; mt++) {
                uint32_t addr = aB + (m_w + mt * 16 + (lane & 15)) * 80
                              + k16 * 32 + ((lane >> 4) & 1) * 16;
                ldmatrix_x4(a[mt], addr);
            }
#pragma unroll
            for (int nt = 0; nt < 8; nt++) {
                uint32_t b0, b1;
                uint32_t baddr = bB + (k16 * 16 + (lane & 15)) * 528
                               + (n_w + nt * 8) * 2;
                ldmatrix_x2t(b0, b1, baddr);
#pragma unroll
                for (int mt = 0; mt < 4; mt++)
                    mma_f16(acc[mt][nt], a[mt], b0, b1);
            }
        }
    }

    if (MODE == 0) {
        __half* Cb = g_qkvh + (size_t)b * CDIM * HW;
#pragma unroll
        for (int mt = 0; mt < 4; mt++) {
            int r0 = m0 + m_w + mt * 16 + gid;
            int r1 = r0 + 8;
#pragma unroll
            for (int nt = 0; nt < 8; nt++) {
                int n = n0 + n_w + nt * 8 + tg * 2;
                if (r0 < MLIM)
                    *(uint32_t*)(Cb + (size_t)r0 * HW + n) = pack2(acc[mt][nt][0], acc[mt][nt][1]);
                if (r1 < MLIM)
                    *(uint32_t*)(Cb + (size_t)r1 * HW + n) = pack2(acc[mt][nt][2], acc[mt][nt][3]);
            }
        }
    } else {
        float* Cb = Cout + (size_t)b * DIM * HW;
#pragma unroll
        for (int mt = 0; mt < 4; mt++) {
            int r0 = m0 + m_w + mt * 16 + gid;
            int r1 = r0 + 8;
#pragma unroll
            for (int nt = 0; nt < 8; nt++) {
                int n = n0 + n_w + nt * 8 + tg * 2;
                if (r0 < MLIM)
                    *(float2*)(Cb + (size_t)r0 * HW + n) = make_float2(acc[mt][nt][0], acc[mt][nt][1]);
                if (r1 < MLIM)
                    *(float2*)(Cb + (size_t)r1 * HW + n) = make_float2(acc[mt][nt][2], acc[mt][nt][3]);
            }
        }
    }
}

// ---------------- smem-tiled depthwise 3x3, dilations 1/2/3 ------------------
// One CTA per (b,ch) plane. Padded fp32 tile in dynamic smem:
// rows -3..130 (134), cols -4..131 (stride 136). Zero borders -> no branches.
#define CPAD   136
#define CROWS  134
#define CONV_SMEM_BYTES (CROWS * CPAD * 4)   // 72896

template <int D>
__device__ __forceinline__ void conv_one(const float* __restrict__ sp,
                                         int y, int x0,
                                         const float* __restrict__ wr,
                                         float o[4]) {
    float r0[12], r1[12], r2[12];
#pragma unroll
    for (int j = 0; j < 3; j++) {
        *(float4*)&r0[j * 4] = *(const float4*)&sp[(y + 3 - D) * CPAD + x0 + j * 4];
        *(float4*)&r1[j * 4] = *(const float4*)&sp[(y + 3)     * CPAD + x0 + j * 4];
        *(float4*)&r2[j * 4] = *(const float4*)&sp[(y + 3 + D) * CPAD + x0 + j * 4];
    }
#pragma unroll
    for (int x = 0; x < 4; x++) {
        float s = 0.f;
#pragma unroll
        for (int kx = 0; kx < 3; kx++) {
            int idx = 4 + x + (kx - 1) * D;
            s = fmaf(r0[idx], wr[kx],     s);
            s = fmaf(r1[idx], wr[3 + kx], s);
            s = fmaf(r2[idx], wr[6 + kx], s);
        }
        o[x] = s;
    }
}

__global__ __launch_bounds__(256) void k_dwconv(const float* __restrict__ w1,
                                                const float* __restrict__ w2,
                                                const float* __restrict__ w3) {
    extern __shared__ __align__(16) float sp[];
    const int bc = blockIdx.x;              // b*576 + ch
    const int ch = bc % CDIM;
    const int tid = threadIdx.x;
    const __half* in = g_qkvh + (size_t)bc * HW;

    // zero whole padded tile (18224 floats = 4556 float4)
    for (int i = tid; i < (CROWS * CPAD) / 4; i += 256)
        *(float4*)&sp[i * 4] = make_float4(0.f, 0.f, 0.f, 0.f);
    __syncthreads();

    // load + cvt interior
    for (int i = tid; i < HW / 4; i += 256) {
        int y = i >> 5, x = (i & 31) << 2;
        uint2 u = *(const uint2*)(in + y * WIMG + x);
        unp4(u, &sp[(y + 3) * CPAD + x + 4]);
    }
    __syncthreads();

    float wr1[9], wr2[9], wr3[9];
#pragma unroll
    for (int i = 0; i < 9; i++) {
        wr1[i] = __ldg(w1 + ch * 9 + i);
        wr2[i] = __ldg(w2 + ch * 9 + i);
        wr3[i] = __ldg(w3 + ch * 9 + i);
    }

    for (int i = tid; i < HW / 4; i += 256) {
        int y = i >> 5, x0 = (i & 31) << 2;
        size_t obase = (size_t)bc * HW + y * WIMG + x0;
        float o[4];
        uint2 w;
        conv_one<1>(sp, y, x0, wr1, o);
        w.x = pack2(o[0], o[1]); w.y = pack2(o[2], o[3]);
        *(uint2*)(g_conv0h + obase) = w;
        conv_one<2>(sp, y, x0, wr2, o);
        w.x = pack2(o[0], o[1]); w.y = pack2(o[2], o[3]);
        *(uint2*)(g_conv1h + obase) = w;
        conv_one<3>(sp, y, x0, wr3, o);
        w.x = pack2(o[0], o[1]); w.y = pack2(o[2], o[3]);
        *(uint2*)(g_conv2h + obase) = w;
    }
}

// ---------------- Gram Q·K^T + norms, split-K (fp16 in) ----------------------
__global__ __launch_bounds__(64) void k_gram() {
    const int bh = blockIdx.x;
    const int slice = blockIdx.y;
    const int b = bh / 24, rem = bh % 24;
    const int br = rem >> 3, head = rem & 7;
    const __half* conv = (br == 0) ? g_conv0h : (br == 1) ? g_conv1h : g_conv2h;
    const __half* qb = conv + (size_t)(b * CDIM + head * 24) * HW;
    const __half* kb = conv + (size_t)(b * CDIM + 192 + head * 24) * HW;

    __shared__ __align__(16) float qs[24 * 130];
    __shared__ __align__(16) float ks[24 * 130];

    const int tid = threadIdx.x;
    const int rg = tid >> 3, cg = tid & 7;
    float acc[3][3] = {};
    float qq[3] = {}, kk[3] = {};
    const int n0s = slice * 1024;

    for (int cch = 0; cch < 8; cch++) {
        const int n0 = n0s + cch * 128;
#pragma unroll
        for (int i = 0; i < 12; i++) {
            int idx = (i << 6) + tid;
            int row = idx >> 5, c4 = (idx & 31) << 2;
            uint2 qu = *(const uint2*)(qb + (size_t)row * HW + n0 + c4);
            uint2 ku = *(const uint2*)(kb + (size_t)row * HW + n0 + c4);
            unp4(qu, &qs[row * 130 + c4]);
            unp4(ku, &ks[row * 130 + c4]);
        }
        __syncthreads();
#pragma unroll 4
        for (int n = 0; n < 128; n += 2) {
            float2 qv[3], kv[3];
#pragma unroll
            for (int i = 0; i < 3; i++) {
                qv[i] = *(float2*)&qs[(rg * 3 + i) * 130 + n];
                kv[i] = *(float2*)&ks[(cg * 3 + i) * 130 + n];
            }
#pragma unroll
            for (int i = 0; i < 3; i++)
#pragma unroll
                for (int j = 0; j < 3; j++)
                    acc[i][j] += qv[i].x * kv[j].x + qv[i].y * kv[j].y;
            if (cg == 0) {
#pragma unroll
                for (int i = 0; i < 3; i++)
                    qq[i] += qv[i].x * qv[i].x + qv[i].y * qv[i].y;
            }
            if (rg == 0) {
#pragma unroll
                for (int j = 0; j < 3; j++)
                    kk[j] += kv[j].x * kv[j].x + kv[j].y * kv[j].y;
            }
        }
        __syncthreads();
    }
    const int base = (bh * NSLICE + slice) * 24;
#pragma unroll
    for (int i = 0; i < 3; i++)
#pragma unroll
        for (int j = 0; j < 3; j++)
            g_partS[(size_t)(base + rg * 3 + i) * 24 + cg * 3 + j] = acc[i][j];
    if (cg == 0)
#pragma unroll
        for (int i = 0; i < 3; i++) g_partQQ[base + rg * 3 + i] = qq[i];
    if (rg == 0)
#pragma unroll
        for (int j = 0; j < 3; j++) g_partKK[base + cg * 3 + j] = kk[j];
}

// ---------------- reduce, normalize, temperature, softmax --------------------
__global__ __launch_bounds__(576) void k_softmax(const float* __restrict__ temperature) {
    const int bh = blockIdx.x;
    const int head = bh & 7;
    const int t = threadIdx.x;
    const int c = t / 24, d = t % 24;

    float s = 0.f;
    for (int sl = 0; sl < NSLICE; sl++)
        s += g_partS[(size_t)((bh * NSLICE + sl) * 24 + c) * 24 + d];

    __shared__ float nq[24], nk[24], logits[576], rmax[24], rsum[24];
    if (t < 24) {
        float a = 0.f, b2 = 0.f;
        for (int sl = 0; sl < NSLICE; sl++) {
            a  += g_partQQ[(bh * NSLICE + sl) * 24 + t];
            b2 += g_partKK[(bh * NSLICE + sl) * 24 + t];
        }
        nq[t] = fmaxf(sqrtf(a),  1e-12f);
        nk[t] = fmaxf(sqrtf(b2), 1e-12f);
    }
    __syncthreads();
    float lg = s / (nq[c] * nk[d]) * temperature[head];
    logits[t] = lg;
    __syncthreads();
    if (d == 0) {
        float mx = -1e30f;
        for (int j = 0; j < 24; j++) mx = fmaxf(mx, logits[c * 24 + j]);
        float sm = 0.f;
        for (int j = 0; j < 24; j++) sm += expf(logits[c * 24 + j] - mx);
        rmax[c] = mx; rsum[c] = sm;
    }
    __syncthreads();
    g_attn[(size_t)bh * 576 + t] = expf(lg - rmax[c]) / rsum[c];
}

// ---------------- fold proj into attn: M[b,o,col] (fp16 out) -----------------
__global__ __launch_bounds__(192) void k_buildM(const float* __restrict__ wproj) {
    const int blk = blockIdx.x;
    const int b = blk / 24, rem = blk % 24;
    const int br = rem >> 3, head = rem & 7;
    __shared__ float at[576];
    const int t = threadIdx.x;
#pragma unroll
    for (int i = 0; i < 3; i++) at[t + i * 192] = g_attn[(size_t)blk * 576 + t + i * 192];
    __syncthreads();
    const int colbase = br * 192 + head * 24;
    const float* wrow = wproj + (size_t)t * CDIM + colbase;
    __half* mrow = g_Mh + ((size_t)b * DIM + t) * CDIM + colbase;
#pragma unroll 4
    for (int d = 0; d < 24; d++) {
        float s = 0.f;
#pragma unroll
        for (int cc = 0; cc < 24; cc++) s = fmaf(wrow[cc], at[cc * 24 + d], s);
        mrow[d] = __float2half_rn(s);
    }
}

// ---------------- launch ----------------------------------------------------
extern "C" void kernel_launch(void* const* d_in, const int* in_sizes, int n_in,
                              void* d_out, int out_size) {
    const float* x       = (const float*)d_in[0];
    const float* w_qkv   = (const float*)d_in[1];
    const float* w_dw1   = (const float*)d_in[2];
    const float* w_dw2   = (const float*)d_in[3];
    const float* w_dw3   = (const float*)d_in[4];
    const float* w_proj  = (const float*)d_in[5];
    const float* temp    = (const float*)d_in[6];
    float* out = (float*)d_out;

    cudaFuncSetAttribute(k_mma_gemm<0>, cudaFuncAttributeMaxDynamicSharedMemorySize,
                         GEMM_SMEM_BYTES);
    cudaFuncSetAttribute(k_mma_gemm<1>, cudaFuncAttributeMaxDynamicSharedMemorySize,
                         GEMM_SMEM_BYTES);
    cudaFuncSetAttribute(k_dwconv, cudaFuncAttributeMaxDynamicSharedMemorySize,
                         CONV_SMEM_BYTES);

    __half* d_xh;    cudaGetSymbolAddress((void**)&d_xh, g_xh);
    __half* d_wh;    cudaGetSymbolAddress((void**)&d_wh, g_wqkvh);

    k_cvt<<<24576, 256>>>((const float4*)x, (uint2*)d_xh);
    k_cvt<<<108, 256>>>((const float4*)w_qkv, (uint2*)d_wh);

    k_mma_gemm<0><<<dim3(5, 64, NB), 256, GEMM_SMEM_BYTES>>>(nullptr);
    k_dwconv<<<NB * CDIM, 256, CONV_SMEM_BYTES>>>(w_dw1, w_dw2, w_dw3);
    k_gram<<<dim3(NBH, NSLICE), 64>>>();
    k_softmax<<<NBH, 576>>>(temp);
    k_buildM<<<NBH, 192>>>(w_proj);
    k_mma_gemm<1><<<dim3(2, 64, NB), 256, GEMM_SMEM_BYTES>>>(out);
}